// round 6
// baseline (speedup 1.0000x reference)
#include <cuda_runtime.h>
#include <cstdint>

// out = relu(x @ (gamma*W3 + W4)^T)
// (reference softmax is over a size-1 axis == 1.0 -> attention is identity on
//  the W3 branch; W1/W2 are dead inputs)
//
// Persistent single-wave kernel: 148 blocks x 512 threads (1 block/SM).
// Grid-strided 64-row tiles. x tiles double-buffered in smem (LDG stagers).
// NEW: output tiles are built in double-buffered smem (STS.128) and drained
// to GMEM with cp.async.bulk (TMA bulk store) -> guaranteed full-line DRAM
// writes, eliminating L2 write-allocate read traffic that capped R3/R4 at
// ~2.5 TB/s effective.

#define DICT 20
#define OUTC 200
#define NBLK 148
#define TPB 512
#define TILE 64
#define CPT 50                       // column-quad threads per row
#define RLANES 8
#define RPT (TILE / RLANES)          // 8 rows/thread/tile
#define NCOMPUTE (CPT * RLANES)      // 400
#define STAGERS (TILE * DICT / 4)    // 320 float4 per x tile
#define XS_FLOATS (TILE * DICT)      // 1280
#define OB_FLOATS (TILE * OUTC)      // 12800 (50 KB)
#define OB_BYTES (OB_FLOATS * 4)
#define SMEM_BYTES ((2 * XS_FLOATS + 2 * OB_FLOATS) * 4)   // 112,640 B

// ---- packed f32x2 helpers (sm_103a FFMA2 path, PTX-only) ----
__device__ __forceinline__ unsigned long long pack2(float lo, float hi) {
    unsigned long long r;
    asm("mov.b64 %0, {%1, %2};" : "=l"(r) : "f"(lo), "f"(hi));
    return r;
}
__device__ __forceinline__ unsigned long long fma2(unsigned long long a,
                                                   unsigned long long b,
                                                   unsigned long long c) {
    unsigned long long d;
    asm("fma.rn.f32x2 %0, %1, %2, %3;" : "=l"(d) : "l"(a), "l"(b), "l"(c));
    return d;
}
__device__ __forceinline__ unsigned long long mul2(unsigned long long a,
                                                   unsigned long long b) {
    unsigned long long d;
    asm("mul.rn.f32x2 %0, %1, %2;" : "=l"(d) : "l"(a), "l"(b));
    return d;
}
__device__ __forceinline__ float hadd_relu(unsigned long long v) {
    float2 f;
    asm("mov.b64 {%0, %1}, %2;" : "=f"(f.x), "=f"(f.y) : "l"(v));
    return fmaxf(f.x + f.y, 0.0f);
}
__device__ __forceinline__ uint32_t smem_u32(const void* p) {
    uint32_t a;
    asm("{ .reg .u64 t; cvta.to.shared.u64 t, %1; cvt.u32.u64 %0, t; }"
        : "=r"(a) : "l"(p));
    return a;
}

__global__ __launch_bounds__(TPB, 1)
void fused_gemm_relu(const float* __restrict__ x,
                     const float* __restrict__ W3,
                     const float* __restrict__ W4,
                     const float* __restrict__ gamma,
                     float* __restrict__ out, int ntiles) {
    extern __shared__ __align__(16) float smem[];
    float* xs[2] = { smem, smem + XS_FLOATS };
    float* ob[2] = { smem + 2 * XS_FLOATS,
                     smem + 2 * XS_FLOATS + OB_FLOATS };

    const int tid = threadIdx.x;
    const int cp = tid % CPT;                 // cols [4cp, 4cp+4)
    const int rl = tid / CPT;                 // row lane 0..7
    const bool is_compute = (tid < NCOMPUTE);
    const bool is_stager  = (tid < STAGERS);

    // Build this thread's 4 combined weight rows in registers (packed f32x2).
    unsigned long long w0[10], w1[10], w2[10], w3[10];
    if (is_compute) {
        const float g = gamma[0];
        #pragma unroll
        for (int c = 0; c < 4; c++) {
            unsigned long long* wc = (c == 0) ? w0 : (c == 1) ? w1
                                   : (c == 2) ? w2 : w3;
            const float4* p3 = reinterpret_cast<const float4*>(W3 + (4 * cp + c) * DICT);
            const float4* p4 = reinterpret_cast<const float4*>(W4 + (4 * cp + c) * DICT);
            #pragma unroll
            for (int i = 0; i < 5; i++) {
                float4 a = p3[i], b = p4[i];
                wc[2 * i]     = pack2(fmaf(g, a.x, b.x), fmaf(g, a.y, b.y));
                wc[2 * i + 1] = pack2(fmaf(g, a.z, b.z), fmaf(g, a.w, b.w));
            }
        }
    }

    // Prologue: stage this block's first x tile.
    if (blockIdx.x < ntiles && is_stager)
        *reinterpret_cast<float4*>(&xs[0][tid * 4]) =
            reinterpret_cast<const float4*>(x + (size_t)blockIdx.x * XS_FLOATS)[tid];
    __syncthreads();

    int buf = 0;
    for (int t = blockIdx.x; t < ntiles; t += NBLK, buf ^= 1) {
        // Ensure ob[buf]'s previous bulk store (2 tiles ago) has drained.
        if (tid == 0)
            asm volatile("cp.async.bulk.wait_group 1;" ::: "memory");
        __syncthreads();

        // Prefetch next x tile into the other buffer (overlaps compute).
        const int tn = t + NBLK;
        if (tn < ntiles && is_stager)
            *reinterpret_cast<float4*>(&xs[buf ^ 1][tid * 4]) =
                reinterpret_cast<const float4*>(x + (size_t)tn * XS_FLOATS)[tid];

        if (is_compute) {
            const float* xb = xs[buf];
            float4* o = reinterpret_cast<float4*>(ob[buf]) + rl * (OUTC / 4) + cp;
            #pragma unroll
            for (int i = 0; i < RPT; i++) {
                const ulonglong2* xp = reinterpret_cast<const ulonglong2*>(
                    xb + (rl + i * RLANES) * DICT);
                ulonglong2 v0 = xp[0], v1 = xp[1], v2 = xp[2],
                           v3 = xp[3], v4 = xp[4];

                unsigned long long a0, a1, a2, a3;
                a0 = mul2(v0.x, w0[0]);      a1 = mul2(v0.x, w1[0]);
                a2 = mul2(v0.x, w2[0]);      a3 = mul2(v0.x, w3[0]);
                a0 = fma2(v0.y, w0[1], a0);  a1 = fma2(v0.y, w1[1], a1);
                a2 = fma2(v0.y, w2[1], a2);  a3 = fma2(v0.y, w3[1], a3);
                a0 = fma2(v1.x, w0[2], a0);  a1 = fma2(v1.x, w1[2], a1);
                a2 = fma2(v1.x, w2[2], a2);  a3 = fma2(v1.x, w3[2], a3);
                a0 = fma2(v1.y, w0[3], a0);  a1 = fma2(v1.y, w1[3], a1);
                a2 = fma2(v1.y, w2[3], a2);  a3 = fma2(v1.y, w3[3], a3);
                a0 = fma2(v2.x, w0[4], a0);  a1 = fma2(v2.x, w1[4], a1);
                a2 = fma2(v2.x, w2[4], a2);  a3 = fma2(v2.x, w3[4], a3);
                a0 = fma2(v2.y, w0[5], a0);  a1 = fma2(v2.y, w1[5], a1);
                a2 = fma2(v2.y, w2[5], a2);  a3 = fma2(v2.y, w3[5], a3);
                a0 = fma2(v3.x, w0[6], a0);  a1 = fma2(v3.x, w1[6], a1);
                a2 = fma2(v3.x, w2[6], a2);  a3 = fma2(v3.x, w3[6], a3);
                a0 = fma2(v3.y, w0[7], a0);  a1 = fma2(v3.y, w1[7], a1);
                a2 = fma2(v3.y, w2[7], a2);  a3 = fma2(v3.y, w3[7], a3);
                a0 = fma2(v4.x, w0[8], a0);  a1 = fma2(v4.x, w1[8], a1);
                a2 = fma2(v4.x, w2[8], a2);  a3 = fma2(v4.x, w3[8], a3);
                a0 = fma2(v4.y, w0[9], a0);  a1 = fma2(v4.y, w1[9], a1);
                a2 = fma2(v4.y, w2[9], a2);  a3 = fma2(v4.y, w3[9], a3);

                *o = make_float4(hadd_relu(a0), hadd_relu(a1),
                                 hadd_relu(a2), hadd_relu(a3));  // STS.128
                o += RLANES * (OUTC / 4);    // 8 rows ahead in smem
            }
        }
        __syncthreads();   // ob[buf] complete; xs[buf^1] staged

        // Drain ob[buf] -> out with a TMA bulk store (full-line writes).
        if (tid == 0) {
            asm volatile("fence.proxy.async.shared::cta;" ::: "memory");
            uint32_t src = smem_u32(ob[buf]);
            const float* dst = out + (size_t)t * OB_FLOATS;
            asm volatile(
                "cp.async.bulk.global.shared::cta.bulk_group [%0], [%1], %2;"
                :: "l"(dst), "r"(src), "n"(OB_BYTES) : "memory");
            asm volatile("cp.async.bulk.commit_group;" ::: "memory");
        }
    }

    // Let outstanding bulk stores complete before the block exits.
    if (tid == 0)
        asm volatile("cp.async.bulk.wait_group 0;" ::: "memory");
}

extern "C" void kernel_launch(void* const* d_in, const int* in_sizes, int n_in,
                              void* d_out, int out_size) {
    const float* x     = (const float*)d_in[0];
    // d_in[1] = W1, d_in[2] = W2 : dead (softmax over size-1 axis == 1)
    const float* W3    = (const float*)d_in[3];
    const float* W4    = (const float*)d_in[4];
    const float* gamma = (const float*)d_in[5];
    float* out = (float*)d_out;

    const int B = in_sizes[0] / DICT;   // 262144
    const int ntiles = B / TILE;        // 4096 (exact)

    static int attr_set = 0;
    if (!attr_set) {
        cudaFuncSetAttribute(fused_gemm_relu,
                             cudaFuncAttributeMaxDynamicSharedMemorySize,
                             SMEM_BYTES);
        attr_set = 1;
    }
    fused_gemm_relu<<<NBLK, TPB, SMEM_BYTES>>>(x, W3, W4, gamma, out, ntiles);
}

// round 7
// speedup vs baseline: 1.1901x; 1.1901x over previous
#include <cuda_runtime.h>
#include <cstdint>

// out = relu(x @ (gamma*W3 + W4)^T)
// (reference softmax is over a size-1 axis == 1.0 -> attention is identity on
//  the W3 branch; W1/W2 are dead inputs)
//
// Persistent single-wave kernel: 148 blocks x 512 threads (1 block/SM).
// Grid-strided 128-row tiles. x tiles staged via cp.async (LDGSTS) into a
// 4-slot smem ring with prefetch distance 4: staging latency is fully
// decoupled from the per-tile critical path (R4's LDG->reg->STS stagers put
// DRAM latency on the barrier path every tile; that was the 67us plateau).
// Compute thread (cp, rl): owns cols [4cp,4cp+4) -> one STG.128 per row;
// rows rl, rl+8, ... of the tile. Weights (4 rows of gamma*W3+W4) live in
// registers as packed f32x2; FFMA2 doubles the fp32 FMA rate.

#define DICT 20
#define OUTC 200
#define NBLK 148
#define TPB 512
#define TILE 128
#define NSLOT 4
#define CPT 50                       // column-quad threads per row
#define RLANES 8
#define RPT (TILE / RLANES)          // 16 rows/thread/tile
#define NCOMPUTE (CPT * RLANES)      // 400
#define XS_FLOATS (TILE * DICT)      // 2560 floats (10 KB per slot)
#define CPN (XS_FLOATS / 4)          // 640 16-byte copies per tile

// ---- packed f32x2 helpers (sm_103a FFMA2 path, PTX-only) ----
__device__ __forceinline__ unsigned long long pack2(float lo, float hi) {
    unsigned long long r;
    asm("mov.b64 %0, {%1, %2};" : "=l"(r) : "f"(lo), "f"(hi));
    return r;
}
__device__ __forceinline__ unsigned long long fma2(unsigned long long a,
                                                   unsigned long long b,
                                                   unsigned long long c) {
    unsigned long long d;
    asm("fma.rn.f32x2 %0, %1, %2, %3;" : "=l"(d) : "l"(a), "l"(b), "l"(c));
    return d;
}
__device__ __forceinline__ unsigned long long mul2(unsigned long long a,
                                                   unsigned long long b) {
    unsigned long long d;
    asm("mul.rn.f32x2 %0, %1, %2;" : "=l"(d) : "l"(a), "l"(b));
    return d;
}
__device__ __forceinline__ float hadd_relu(unsigned long long v) {
    float2 f;
    asm("mov.b64 {%0, %1}, %2;" : "=f"(f.x), "=f"(f.y) : "l"(v));
    return fmaxf(f.x + f.y, 0.0f);
}
__device__ __forceinline__ uint32_t smem_u32(const void* p) {
    uint32_t a;
    asm("{ .reg .u64 t; cvta.to.shared.u64 t, %1; cvt.u32.u64 %0, t; }"
        : "=r"(a) : "l"(p));
    return a;
}
__device__ __forceinline__ void cp_async16(uint32_t dst, const void* src) {
    asm volatile("cp.async.cg.shared.global [%0], [%1], 16;"
                 :: "r"(dst), "l"(src) : "memory");
}

__global__ __launch_bounds__(TPB, 1)
void fused_gemm_relu(const float* __restrict__ x,
                     const float* __restrict__ W3,
                     const float* __restrict__ W4,
                     const float* __restrict__ gamma,
                     float* __restrict__ out, int ntiles) {
    __shared__ __align__(16) float xs[NSLOT][XS_FLOATS];   // 40 KB

    const int tid = threadIdx.x;
    const int cp = tid % CPT;                 // cols [4cp, 4cp+4)
    const int rl = tid / CPT;                 // row lane 0..7
    const bool is_compute = (tid < NCOMPUTE);

    // Build this thread's 4 combined weight rows in registers (packed f32x2).
    unsigned long long w0[10], w1[10], w2[10], w3[10];
    if (is_compute) {
        const float g = gamma[0];
        #pragma unroll
        for (int c = 0; c < 4; c++) {
            unsigned long long* wc = (c == 0) ? w0 : (c == 1) ? w1
                                   : (c == 2) ? w2 : w3;
            const float4* p3 = reinterpret_cast<const float4*>(W3 + (4 * cp + c) * DICT);
            const float4* p4 = reinterpret_cast<const float4*>(W4 + (4 * cp + c) * DICT);
            #pragma unroll
            for (int i = 0; i < 5; i++) {
                float4 a = p3[i], b = p4[i];
                wc[2 * i]     = pack2(fmaf(g, a.x, b.x), fmaf(g, a.y, b.y));
                wc[2 * i + 1] = pack2(fmaf(g, a.z, b.z), fmaf(g, a.w, b.w));
            }
        }
    }

    // Prologue: issue staging for the first NSLOT tiles (one group per tile).
    #pragma unroll
    for (int k = 0; k < NSLOT; k++) {
        const int tn = blockIdx.x + k * NBLK;
        if (tn < ntiles) {
            const float4* src =
                reinterpret_cast<const float4*>(x + (size_t)tn * XS_FLOATS);
            for (int i = tid; i < CPN; i += TPB)
                cp_async16(smem_u32(&xs[k][i * 4]), src + i);
        }
        asm volatile("cp.async.commit_group;" ::: "memory");
    }

    int slot = 0;
    for (int t = blockIdx.x; t < ntiles; t += NBLK) {
        // Tile t's staging group is the oldest pending; allow 3 newer pending.
        asm volatile("cp.async.wait_group 3;" ::: "memory");
        __syncthreads();                       // all threads' copies visible

        if (is_compute) {
            const float* xb = xs[slot];
            float4* o = reinterpret_cast<float4*>(
                            out + (size_t)(t * TILE + rl) * OUTC) + cp;
            #pragma unroll
            for (int i = 0; i < RPT; i++) {
                const ulonglong2* xp = reinterpret_cast<const ulonglong2*>(
                    xb + (rl + i * RLANES) * DICT);
                ulonglong2 v0 = xp[0], v1 = xp[1], v2 = xp[2],
                           v3 = xp[3], v4 = xp[4];

                unsigned long long a0, a1, a2, a3;
                a0 = mul2(v0.x, w0[0]);      a1 = mul2(v0.x, w1[0]);
                a2 = mul2(v0.x, w2[0]);      a3 = mul2(v0.x, w3[0]);
                a0 = fma2(v0.y, w0[1], a0);  a1 = fma2(v0.y, w1[1], a1);
                a2 = fma2(v0.y, w2[1], a2);  a3 = fma2(v0.y, w3[1], a3);
                a0 = fma2(v1.x, w0[2], a0);  a1 = fma2(v1.x, w1[2], a1);
                a2 = fma2(v1.x, w2[2], a2);  a3 = fma2(v1.x, w3[2], a3);
                a0 = fma2(v1.y, w0[3], a0);  a1 = fma2(v1.y, w1[3], a1);
                a2 = fma2(v1.y, w2[3], a2);  a3 = fma2(v1.y, w3[3], a3);
                a0 = fma2(v2.x, w0[4], a0);  a1 = fma2(v2.x, w1[4], a1);
                a2 = fma2(v2.x, w2[4], a2);  a3 = fma2(v2.x, w3[4], a3);
                a0 = fma2(v2.y, w0[5], a0);  a1 = fma2(v2.y, w1[5], a1);
                a2 = fma2(v2.y, w2[5], a2);  a3 = fma2(v2.y, w3[5], a3);
                a0 = fma2(v3.x, w0[6], a0);  a1 = fma2(v3.x, w1[6], a1);
                a2 = fma2(v3.x, w2[6], a2);  a3 = fma2(v3.x, w3[6], a3);
                a0 = fma2(v3.y, w0[7], a0);  a1 = fma2(v3.y, w1[7], a1);
                a2 = fma2(v3.y, w2[7], a2);  a3 = fma2(v3.y, w3[7], a3);
                a0 = fma2(v4.x, w0[8], a0);  a1 = fma2(v4.x, w1[8], a1);
                a2 = fma2(v4.x, w2[8], a2);  a3 = fma2(v4.x, w3[8], a3);
                a0 = fma2(v4.y, w0[9], a0);  a1 = fma2(v4.y, w1[9], a1);
                a2 = fma2(v4.y, w2[9], a2);  a3 = fma2(v4.y, w3[9], a3);

                *o = make_float4(hadd_relu(a0), hadd_relu(a1),
                                 hadd_relu(a2), hadd_relu(a3));  // STG.128
                o += RLANES * (OUTC / 4);    // 8 rows ahead
            }
        }
        __syncthreads();                       // slot fully consumed

        // Refill this slot with tile t + NSLOT*NBLK (may be empty group).
        const int tn = t + NSLOT * NBLK;
        if (tn < ntiles) {
            const float4* src =
                reinterpret_cast<const float4*>(x + (size_t)tn * XS_FLOATS);
            for (int i = tid; i < CPN; i += TPB)
                cp_async16(smem_u32(&xs[slot][i * 4]), src + i);
        }
        asm volatile("cp.async.commit_group;" ::: "memory");

        slot = (slot + 1) & (NSLOT - 1);
    }
}

extern "C" void kernel_launch(void* const* d_in, const int* in_sizes, int n_in,
                              void* d_out, int out_size) {
    const float* x     = (const float*)d_in[0];
    // d_in[1] = W1, d_in[2] = W2 : dead (softmax over size-1 axis == 1)
    const float* W3    = (const float*)d_in[3];
    const float* W4    = (const float*)d_in[4];
    const float* gamma = (const float*)d_in[5];
    float* out = (float*)d_out;

    const int B = in_sizes[0] / DICT;   // 262144
    const int ntiles = B / TILE;        // 2048 (exact)

    fused_gemm_relu<<<NBLK, TPB>>>(x, W3, W4, gamma, out, ntiles);
}

// round 9
// speedup vs baseline: 1.2436x; 1.0450x over previous
#include <cuda_runtime.h>
#include <cstdint>

// out = relu(x @ (gamma*W3 + W4)^T)
// (reference softmax is over a size-1 axis == 1.0 -> attention is identity on
//  the W3 branch; W1/W2 are dead inputs)
//
// Persistent single-wave kernel: 148 blocks x 800 threads (1 block/SM,
// 25 warps). Grid-strided 128-row tiles; x tiles staged via cp.async
// (LDGSTS) into a 4-slot smem ring, prefetch distance 4 (R6 machinery).
// NEW vs R6: 2 output columns per thread (not 4) -> ~60 regs/thread instead
// of 128 -> 25 warps instead of 16. R6 sat at exactly 2x the FFMA2 pipe
// floor because 16 warps at 128 regs could not hide LDS+fma-chain latency;
// the fma pipe floor (~4000 cyc per 128-row tile) needs more resident warps.
// Thread (cp, rl): cols {2cp, 2cp+1}, rows rl, rl+8, ... of the tile.
// Weights (2 rows of gamma*W3+W4) in registers as packed f32x2; FFMA2
// (fma.rn.f32x2) doubles the fp32 FMA rate.

#define DICT 20
#define OUTC 200
#define NBLK 148
#define TPB 800
#define TILE 128
#define NSLOT 4
#define CPT 100                      // column-pair threads per row
#define RLANES 8
#define RPT (TILE / RLANES)          // 16 rows/thread/tile
#define XS_FLOATS (TILE * DICT)      // 2560 floats (10 KB per slot)
#define CPN (XS_FLOATS / 4)          // 640 16-byte copies per tile

// ---- packed f32x2 helpers (sm_103a FFMA2 path, PTX-only) ----
__device__ __forceinline__ unsigned long long pack2(float lo, float hi) {
    unsigned long long r;
    asm("mov.b64 %0, {%1, %2};" : "=l"(r) : "f"(lo), "f"(hi));
    return r;
}
__device__ __forceinline__ unsigned long long fma2(unsigned long long a,
                                                   unsigned long long b,
                                                   unsigned long long c) {
    unsigned long long d;
    asm("fma.rn.f32x2 %0, %1, %2, %3;" : "=l"(d) : "l"(a), "l"(b), "l"(c));
    return d;
}
__device__ __forceinline__ unsigned long long mul2(unsigned long long a,
                                                   unsigned long long b) {
    unsigned long long d;
    asm("mul.rn.f32x2 %0, %1, %2;" : "=l"(d) : "l"(a), "l"(b));
    return d;
}
__device__ __forceinline__ float hadd_relu(unsigned long long v) {
    float2 f;
    asm("mov.b64 {%0, %1}, %2;" : "=f"(f.x), "=f"(f.y) : "l"(v));
    return fmaxf(f.x + f.y, 0.0f);
}
__device__ __forceinline__ uint32_t smem_u32(const void* p) {
    uint32_t a;
    asm("{ .reg .u64 t; cvta.to.shared.u64 t, %1; cvt.u32.u64 %0, t; }"
        : "=r"(a) : "l"(p));
    return a;
}
__device__ __forceinline__ void cp_async16(uint32_t dst, const void* src) {
    asm volatile("cp.async.cg.shared.global [%0], [%1], 16;"
                 :: "r"(dst), "l"(src) : "memory");
}

__global__ __launch_bounds__(TPB, 1)
void fused_gemm_relu(const float* __restrict__ x,
                     const float* __restrict__ W3,
                     const float* __restrict__ W4,
                     const float* __restrict__ gamma,
                     float* __restrict__ out, int ntiles) {
    __shared__ __align__(16) float xs[NSLOT][XS_FLOATS];   // 40 KB

    const int tid = threadIdx.x;
    const int cp = tid % CPT;                 // cols {2cp, 2cp+1}
    const int rl = tid / CPT;                 // row lane 0..7

    // Build this thread's 2 combined weight rows in registers (packed f32x2).
    unsigned long long w0[10], w1[10];
    {
        const float g = gamma[0];
        const float4* a3 = reinterpret_cast<const float4*>(W3 + (2 * cp) * DICT);
        const float4* a4 = reinterpret_cast<const float4*>(W4 + (2 * cp) * DICT);
        const float4* b3 = reinterpret_cast<const float4*>(W3 + (2 * cp + 1) * DICT);
        const float4* b4 = reinterpret_cast<const float4*>(W4 + (2 * cp + 1) * DICT);
        #pragma unroll
        for (int i = 0; i < 5; i++) {
            float4 p3 = a3[i], p4 = a4[i];
            w0[2 * i]     = pack2(fmaf(g, p3.x, p4.x), fmaf(g, p3.y, p4.y));
            w0[2 * i + 1] = pack2(fmaf(g, p3.z, p4.z), fmaf(g, p3.w, p4.w));
            float4 q3 = b3[i], q4 = b4[i];
            w1[2 * i]     = pack2(fmaf(g, q3.x, q4.x), fmaf(g, q3.y, q4.y));
            w1[2 * i + 1] = pack2(fmaf(g, q3.z, q4.z), fmaf(g, q3.w, q4.w));
        }
    }

    // Prologue: issue staging for the first NSLOT tiles (one group per tile).
    #pragma unroll
    for (int k = 0; k < NSLOT; k++) {
        const int tn = blockIdx.x + k * NBLK;
        if (tn < ntiles && tid < CPN) {
            const float4* src =
                reinterpret_cast<const float4*>(x + (size_t)tn * XS_FLOATS);
            cp_async16(smem_u32(&xs[k][tid * 4]), src + tid);
        }
        asm volatile("cp.async.commit_group;" ::: "memory");
    }

    int slot = 0;
    for (int t = blockIdx.x; t < ntiles; t += NBLK) {
        // Tile t's staging group is the oldest pending; allow 3 newer pending.
        asm volatile("cp.async.wait_group 3;" ::: "memory");
        __syncthreads();                       // all threads' copies visible

        {
            const float* xb = xs[slot];
            float2* o = reinterpret_cast<float2*>(
                            out + (size_t)(t * TILE + rl) * OUTC) + cp;
            #pragma unroll
            for (int i = 0; i < RPT; i++) {
                const ulonglong2* xp = reinterpret_cast<const ulonglong2*>(
                    xb + (rl + i * RLANES) * DICT);
                ulonglong2 v0 = xp[0], v1 = xp[1], v2 = xp[2],
                           v3 = xp[3], v4 = xp[4];

                unsigned long long a0, a1;
                a0 = mul2(v0.x, w0[0]);      a1 = mul2(v0.x, w1[0]);
                a0 = fma2(v0.y, w0[1], a0);  a1 = fma2(v0.y, w1[1], a1);
                a0 = fma2(v1.x, w0[2], a0);  a1 = fma2(v1.x, w1[2], a1);
                a0 = fma2(v1.y, w0[3], a0);  a1 = fma2(v1.y, w1[3], a1);
                a0 = fma2(v2.x, w0[4], a0);  a1 = fma2(v2.x, w1[4], a1);
                a0 = fma2(v2.y, w0[5], a0);  a1 = fma2(v2.y, w1[5], a1);
                a0 = fma2(v3.x, w0[6], a0);  a1 = fma2(v3.x, w1[6], a1);
                a0 = fma2(v3.y, w0[7], a0);  a1 = fma2(v3.y, w1[7], a1);
                a0 = fma2(v4.x, w0[8], a0);  a1 = fma2(v4.x, w1[8], a1);
                a0 = fma2(v4.y, w0[9], a0);  a1 = fma2(v4.y, w1[9], a1);

                *o = make_float2(hadd_relu(a0), hadd_relu(a1));  // STG.64
                o += RLANES * (OUTC / 2);    // 8 rows ahead
            }
        }
        __syncthreads();                       // slot fully consumed

        // Refill this slot with tile t + NSLOT*NBLK (may be empty group).
        const int tn = t + NSLOT * NBLK;
        if (tn < ntiles && tid < CPN) {
            const float4* src =
                reinterpret_cast<const float4*>(x + (size_t)tn * XS_FLOATS);
            cp_async16(smem_u32(&xs[slot][tid * 4]), src + tid);
        }
        asm volatile("cp.async.commit_group;" ::: "memory");

        slot = (slot + 1) & (NSLOT - 1);
    }
}

extern "C" void kernel_launch(void* const* d_in, const int* in_sizes, int n_in,
                              void* d_out, int out_size) {
    const float* x     = (const float*)d_in[0];
    // d_in[1] = W1, d_in[2] = W2 : dead (softmax over size-1 axis == 1)
    const float* W3    = (const float*)d_in[3];
    const float* W4    = (const float*)d_in[4];
    const float* gamma = (const float*)d_in[5];
    float* out = (float*)d_out;

    const int B = in_sizes[0] / DICT;   // 262144
    const int ntiles = B / TILE;        // 2048 (exact)

    fused_gemm_relu<<<NBLK, TPB>>>(x, W3, W4, gamma, out, ntiles);
}